// round 17
// baseline (speedup 1.0000x reference)
#include <cuda_runtime.h>
#include <cuda_bf16.h>
#include <cstdint>

#define T_FRAMES 16384
#define E_DIM    1024
#define M_MODELS 8
#define K_CLUST  512

#define TM   64
#define TNQ  128                // cols per quarter tile
#define NQ   4                  // quarters
#define KBLK 128
#define NSTAGE (E_DIM / KBLK)   // 8
#define MAXT_G 34
#define NTHREADS 512
#define TAU  20.0f
#define CAP  1024

#define B_FULL_STAGE 65536      // full-model stage stride in g_cent_s8
#define B_Q_STAGE    16384      // quarter stage bytes

// ---- persistent scratch ----
__device__ uint8_t g_cent_s8[M_MODELS * NSTAGE * B_FULL_STAGE];   // 4.2MB
__device__ int   g_counts[M_MODELS];       // zero at load; re-zeroed by fused tail
__device__ int   g_done;                   // grid arrival counter (self-resetting)
__device__ int   g_qdone[M_MODELS * 64];   // per-(m,mt) quarter counters (self-resetting)
__device__ int   g_rows[M_MODELS * T_FRAMES];
__device__ float g_chalf[M_MODELS * K_CLUST];
__device__ unsigned long long g_packed[T_FRAMES];   // re-armed each call in prep

// ================= helpers =================
__device__ __forceinline__ uint32_t smem_u32(const void* p) {
    uint32_t a;
    asm("{ .reg .u64 t; cvta.to.shared.u64 t, %1; cvt.u32.u64 %0, t; }" : "=r"(a) : "l"(p));
    return a;
}
__device__ __forceinline__ void bulk_g2s(uint32_t dst, const void* src,
                                         uint32_t bytes, uint32_t mbar) {
    asm volatile(
        "cp.async.bulk.shared::cluster.global.mbarrier::complete_tx::bytes [%0], [%1], %2, [%3];"
        :: "r"(dst), "l"(src), "r"(bytes), "r"(mbar) : "memory");
}
#define MBARRIER_INIT(addr, cnt) \
    asm volatile("mbarrier.init.shared.b64 [%0], %1;" :: "r"((uint32_t)(addr)), "r"((uint32_t)(cnt)) : "memory")
#define MBARRIER_EXPECT_TX(addr, bytes) \
    asm volatile("mbarrier.arrive.expect_tx.shared.b64 _, [%0], %1;" \
                 :: "r"((uint32_t)(addr)), "r"((uint32_t)(bytes)) : "memory")
#define MBARRIER_WAIT_PARITY(addr, par) do { \
    uint32_t _mb = (uint32_t)(addr); uint32_t _pr = (uint32_t)(par); uint32_t _done; \
    asm volatile("{\n\t.reg .pred p;\n\t" \
        "mbarrier.try_wait.parity.acquire.cta.shared::cta.b64 p, [%1], %2;\n\t" \
        "selp.b32 %0, 1, 0, p;\n\t}" : "=r"(_done) : "r"(_mb), "r"(_pr) : "memory"); \
    if (!_done) { \
        asm volatile("{\n\t.reg .pred P1;\n\t" \
            "WL_%=:\n\t" \
            "mbarrier.try_wait.parity.acquire.cta.shared::cta.b64 P1, [%0], %1, 0x989680;\n\t" \
            "@P1 bra.uni WD_%=;\n\t" \
            "bra.uni WL_%=;\n\t" \
            "WD_%=:\n\t}" :: "r"(_mb), "r"(_pr) : "memory"); \
    } } while (0)
__device__ __forceinline__ void ldmx4(uint32_t addr, uint32_t& r0, uint32_t& r1,
                                      uint32_t& r2, uint32_t& r3) {
    asm volatile("ldmatrix.sync.aligned.m8n8.x4.shared.b16 {%0,%1,%2,%3}, [%4];"
                 : "=r"(r0), "=r"(r1), "=r"(r2), "=r"(r3) : "r"(addr));
}
__device__ __forceinline__ void mma_fp8(float* c, uint32_t a0, uint32_t a1,
                                        uint32_t a2, uint32_t a3,
                                        uint32_t b0, uint32_t b1) {
    asm volatile(
        "mma.sync.aligned.m16n8k32.row.col.f32.e4m3.e4m3.f32 "
        "{%0,%1,%2,%3}, {%4,%5,%6,%7}, {%8,%9}, {%0,%1,%2,%3};"
        : "+f"(c[0]), "+f"(c[1]), "+f"(c[2]), "+f"(c[3])
        : "r"(a0), "r"(a1), "r"(a2), "r"(a3), "r"(b0), "r"(b1));
}
__device__ __forceinline__ unsigned int fkey(float f) {
    unsigned u = __float_as_uint(f);
    return (u & 0x80000000u) ? ~u : (u | 0x80000000u);
}
__device__ __forceinline__ uint32_t f4_to_fp8(float4 v) {
    uint32_t p;
    asm("{ .reg .b16 lo, hi;\n\t"
        "cvt.rn.satfinite.e4m3x2.f32 lo, %2, %1;\n\t"
        "cvt.rn.satfinite.e4m3x2.f32 hi, %4, %3;\n\t"
        "mov.b32 %0, {lo, hi}; }"
        : "=r"(p) : "f"(v.x), "f"(v.y), "f"(v.z), "f"(v.w));
    return p;
}

// ================= smem layout (bytes) =================
#define SM_B      0                        // 2 x 16KB
#define SM_A      32768                    // 2 x 8KB
#define SM_CHALF  49152                    // 128 f32
#define SM_ROWIDX 49664                    // 64 int
#define SM_THR    49920                    // 64 f32
#define SM_PMIN   50176                    // 64 x 4 f32
#define SM_CODE   51200                    // 64 int
#define SM_MBAR   51456                    // 2 x 8B
#define SM_CNT    51472                    // 2 ints (+pad)
#define SM_CAND   51488                    // CAP ints
#define SMEM_TOTAL (51488 + CAP * 4 + 32)  // ~55.6KB -> 2 CTAs/SM

// ================= prep: bucket + g_packed arm + cent pack/chalf =================
__global__ void prep_kernel(const float* __restrict__ cent,
                            const int* __restrict__ model_idx) {
    int gt = blockIdx.x * blockDim.x + threadIdx.x;
    if (gt < T_FRAMES) {
        g_packed[gt] = 0xFFFFFFFFFFFFFFFFull;       // re-arm merge slots
        int mm = model_idx[gt];
        int pos = atomicAdd(&g_counts[mm], 1);      // g_counts zero (load / fused tail)
        g_rows[mm * T_FRAMES + pos] = gt;
    }
    int warp = gt >> 5;
    int lane = threadIdx.x & 31;
    if (warp < M_MODELS * K_CLUST) {
        const int m = warp >> 9;
        const int r = warp & 511;
        const float4* src = reinterpret_cast<const float4*>(cent + (size_t)warp * E_DIM);
        uint8_t* base = g_cent_s8 + (size_t)m * NSTAGE * B_FULL_STAGE;
        const uint32_t sw16 = ((lane >> 2) ^ (r & 7)) << 4;
        const uint32_t boff = (lane & 3) * 4;
        float s = 0.f;
        #pragma unroll
        for (int q = 0; q < 8; ++q) {
            float4 v = src[lane + 32 * q];
            *reinterpret_cast<uint32_t*>(base + q * B_FULL_STAGE + r * 128 + sw16 + boff)
                = f4_to_fp8(v);
            s += v.x * v.x + v.y * v.y + v.z * v.z + v.w * v.w;
        }
        #pragma unroll
        for (int o = 16; o; o >>= 1) s += __shfl_xor_sync(0xffffffffu, s, o);
        if (lane == 0) g_chalf[warp] = 0.5f * s;
    }
}

// ================= fused quarter-tile GEMM + argmin + rescore + gather =================
// grid = (M_MODELS*MAXT_G, NQ): m = bx/MAXT_G, mtb = bx%MAXT_G, nt = by
__global__ __launch_bounds__(NTHREADS, 2)
void fused_kernel(const float* __restrict__ emb, const float* __restrict__ cent,
                  float* __restrict__ out) {
    extern __shared__ char smem[];
    const uint32_t sb = smem_u32(smem);

    const int m   = blockIdx.x / MAXT_G;
    const int mtb = blockIdx.x % MAXT_G;
    const int nt  = blockIdx.y;
    const int cnt = g_counts[m];
    const int ntiles = (cnt + TM - 1) / TM;
    const int* rowsm = g_rows + m * T_FRAMES;

    const int tid  = threadIdx.x;
    const int wid  = tid >> 5;
    const int lane = tid & 31;
    const int wr = wid >> 2;      // 0..3 : 16-frame row group
    const int wc = wid & 3;       // 0..3 : 32-centroid col group

    int*   rowidx_s = reinterpret_cast<int*>(smem + SM_ROWIDX);
    float* chalf_s  = reinterpret_cast<float*>(smem + SM_CHALF);
    float* thr_s    = reinterpret_cast<float*>(smem + SM_THR);
    float* pmin_s   = reinterpret_cast<float*>(smem + SM_PMIN);
    int* code_s = reinterpret_cast<int*>(smem + SM_CODE);
    int* cnt_s  = reinterpret_cast<int*>(smem + SM_CNT);
    int* cand_s = reinterpret_cast<int*>(smem + SM_CAND);

    if (tid < TNQ) chalf_s[tid] = g_chalf[m * K_CLUST + nt * TNQ + tid];
    if (tid == 0) {
        MBARRIER_INIT(sb + SM_MBAR, 1);
        MBARRIER_INIT(sb + SM_MBAR + 8, 1);
    }
    __syncthreads();

    const uint8_t* bsrc = g_cent_s8 + (size_t)m * NSTAGE * B_FULL_STAGE + nt * B_Q_STAGE;
    const float4* emb4  = reinterpret_cast<const float4*>(emb);
    const float4* cent4 = reinterpret_cast<const float4*>(cent);

    const int ar = tid >> 3, ac = tid & 7;          // A: row 0..63, 16B chunk 0..7
    const uint32_t ad = ar * 128 + ((ac ^ (ar & 7)) << 4);
    const int arow_l = wr * 16 + (lane & 7) + ((lane >> 3) & 1) * 8;
    const int brow_b = wc * 32 + (lane & 7) + ((lane >> 3) & 1) * 8;
    const int clane  = lane >> 4;
    const int gid = lane >> 2, tig = lane & 3;

    uint32_t par[2] = {0, 0};

    for (int mt = mtb; mt < ntiles; mt += MAXT_G) {
        __syncthreads();
        if (tid < TM) {
            int gr = mt * TM + tid;
            rowidx_s[tid] = rowsm[min(gr, cnt - 1)];
        }
        if (tid == 0) { cnt_s[0] = 0; cnt_s[1] = 0; }
        __syncthreads();

        const float4* aS = emb4 + (size_t)rowidx_s[ar] * 256 + ac * 4;

        float acc[4][4];
        #pragma unroll
        for (int n = 0; n < 4; ++n)
            #pragma unroll
            for (int r = 0; r < 4; ++r) acc[n][r] = 0.f;

        if (tid == 0) {
            MBARRIER_EXPECT_TX(sb + SM_MBAR, B_Q_STAGE);
            bulk_g2s(sb + SM_B, bsrc, B_Q_STAGE, sb + SM_MBAR);
        }
        float4 ap0 = aS[0], ap1 = aS[1], ap2 = aS[2], ap3 = aS[3];

        for (int kb = 0; kb < NSTAGE; ++kb) {
            const int buf = kb & 1;
            const uint32_t Ab = sb + SM_A + buf * 8192;
            const uint32_t Bb = sb + SM_B + buf * B_Q_STAGE;
            *reinterpret_cast<uint4*>(smem + SM_A + buf * 8192 + ad) =
                make_uint4(f4_to_fp8(ap0), f4_to_fp8(ap1), f4_to_fp8(ap2), f4_to_fp8(ap3));
            if (kb + 1 < NSTAGE) {
                ap0 = aS[(kb + 1) * 32];     ap1 = aS[(kb + 1) * 32 + 1];
                ap2 = aS[(kb + 1) * 32 + 2]; ap3 = aS[(kb + 1) * 32 + 3];
            }
            if (buf == 0) { MBARRIER_WAIT_PARITY(sb + SM_MBAR, par[0]); par[0] ^= 1; }
            else          { MBARRIER_WAIT_PARITY(sb + SM_MBAR + 8, par[1]); par[1] ^= 1; }
            __syncthreads();
            if (kb + 1 < NSTAGE && tid == 0) {
                const int nb = (kb + 1) & 1;
                MBARRIER_EXPECT_TX(sb + SM_MBAR + 8 * nb, B_Q_STAGE);
                bulk_g2s(sb + SM_B + nb * B_Q_STAGE, bsrc + (size_t)(kb + 1) * B_FULL_STAGE,
                         B_Q_STAGE, sb + SM_MBAR + 8 * nb);
            }

            #pragma unroll
            for (int ks = 0; ks < 4; ++ks) {
                const int cc = ks * 2 + clane;
                uint32_t a0, a1, a2, a3;
                ldmx4(Ab + arow_l * 128 + ((cc ^ (arow_l & 7)) << 4), a0, a1, a2, a3);
                uint32_t b[2][4];
                #pragma unroll
                for (int nj = 0; nj < 2; ++nj) {
                    int row = brow_b + nj * 16;
                    ldmx4(Bb + row * 128 + ((cc ^ (row & 7)) << 4),
                          b[nj][0], b[nj][1], b[nj][2], b[nj][3]);
                }
                #pragma unroll
                for (int n = 0; n < 4; ++n)
                    mma_fp8(acc[n], a0, a1, a2, a3,
                            b[n >> 1][n & 1], b[n >> 1][2 + (n & 1)]);
            }
        }

        // ---- per-row local min over this warp's 32 cols ----
        {
            float v0 = __int_as_float(0x7F800000), v1 = v0;
            #pragma unroll
            for (int n = 0; n < 4; ++n) {
                int col = wc * 32 + n * 8 + tig * 2;
                float c0 = chalf_s[col], c1 = chalf_s[col + 1];
                v0 = fminf(v0, fminf(c0 - acc[n][0], c1 - acc[n][1]));
                v1 = fminf(v1, fminf(c0 - acc[n][2], c1 - acc[n][3]));
            }
            #pragma unroll
            for (int o = 1; o < 4; o <<= 1) {
                v0 = fminf(v0, __shfl_xor_sync(0xffffffffu, v0, o));
                v1 = fminf(v1, __shfl_xor_sync(0xffffffffu, v1, o));
            }
            if (tig == 0) {
                pmin_s[(wr * 16 + gid) * 4 + wc] = v0;
                pmin_s[(wr * 16 + gid + 8) * 4 + wc] = v1;
            }
        }
        __syncthreads();
        if (tid < TM) {
            float v = pmin_s[tid * 4];
            #pragma unroll
            for (int w = 1; w < 4; ++w) v = fminf(v, pmin_s[tid * 4 + w]);
            thr_s[tid] = v + TAU;    // local min + tau: superset of global-thr set
        }
        __syncthreads();

        // ---- collect candidates ----
        #pragma unroll
        for (int n = 0; n < 4; ++n) {
            #pragma unroll
            for (int r = 0; r < 4; ++r) {
                int row = wr * 16 + gid + (r >> 1) * 8;
                int col = wc * 32 + n * 8 + tig * 2 + (r & 1);
                float s = chalf_s[col] - acc[n][r];
                if (s <= thr_s[row]) {
                    int idx = atomicAdd(cnt_s, 1);
                    if (idx < CAP) cand_s[idx] = (row << 16) | col;
                }
            }
        }
        __syncthreads();
        const int ncand = min(cnt_s[0], CAP);

        // ---- exact fp32 rescore -> global packed-key merge ----
        for (int i = wid; i < ncand; i += 16) {
            int rc = cand_s[i];
            int row = rc >> 16, col = rc & 0xFFFF;
            const float4* e4 = emb4 + (size_t)rowidx_s[row] * 256;
            const float4* c4 = cent4 + ((size_t)m * K_CLUST + nt * TNQ + col) * 256;
            float d = 0.f;
            #pragma unroll
            for (int q = 0; q < 8; ++q) {
                float4 ea = e4[q * 32 + lane];
                float4 ca = c4[q * 32 + lane];
                d += ea.x * ca.x + ea.y * ca.y + ea.z * ca.z + ea.w * ca.w;
            }
            #pragma unroll
            for (int o = 16; o; o >>= 1) d += __shfl_xor_sync(0xffffffffu, d, o);
            if (lane == 0 && (mt * TM + row) < cnt) {
                float s = chalf_s[col] - d;   // exact fp32: order-independent merge
                unsigned long long key =
                    ((unsigned long long)fkey(s) << 32) | (unsigned)(nt * TNQ + col);
                atomicMin(&g_packed[rowidx_s[row]], key);
            }
        }
        __syncthreads();

        // ---- completion counter: 4th quarter gathers + writes output rows ----
        if (tid == 0) {
            __threadfence();
            int d = atomicAdd(&g_qdone[m * 64 + mt], 1);
            cnt_s[1] = (d == NQ - 1);
        }
        __syncthreads();
        if (cnt_s[1]) {
            __threadfence();   // acquire: see all quarters' atomicMins
            if (tid < TM)
                code_s[tid] = (int)(unsigned)(g_packed[rowidx_s[tid]] & 0xFFFFFFFFull);
            __syncthreads();
            float4* out4 = reinterpret_cast<float4*>(out);
            for (int idx = tid; idx < TM * 256; idx += NTHREADS) {
                int r = idx >> 8, q = idx & 255;
                if (mt * TM + r < cnt) {
                    out4[(size_t)rowidx_s[r] * 256 + q] =
                        cent4[((size_t)m * K_CLUST + code_s[r]) * 256 + q];
                }
            }
            __syncthreads();
            if (tid == 0) { g_qdone[m * 64 + mt] = 0; __threadfence(); }  // self-reset
        }
    }

    // ---- last block zeroes g_counts for the NEXT call ----
    __syncthreads();
    if (tid == 0) {
        __threadfence();
        int d = atomicAdd(&g_done, 1);
        if (d == (int)(gridDim.x * gridDim.y) - 1) {
            g_done = 0;
            #pragma unroll
            for (int i = 0; i < M_MODELS; ++i) g_counts[i] = 0;
            __threadfence();
        }
    }
}

// ================= launch =================
extern "C" void kernel_launch(void* const* d_in, const int* in_sizes, int n_in,
                              void* d_out, int out_size) {
    const float* emb  = (const float*)d_in[0];
    const float* cent = (const float*)d_in[1];
    const int*   midx = (const int*)d_in[2];
    float* out = (float*)d_out;

    cudaFuncSetAttribute(fused_kernel,
                         cudaFuncAttributeMaxDynamicSharedMemorySize, SMEM_TOTAL);

    prep_kernel<<<(M_MODELS * K_CLUST * 32) / 256, 256>>>(cent, midx);

    dim3 grid(M_MODELS * MAXT_G, NQ);   // (272, 4)
    fused_kernel<<<grid, NTHREADS, SMEM_TOTAL>>>(emb, cent, out);
}